// round 14
// baseline (speedup 1.0000x reference)
#include <cuda_runtime.h>
#include <cuda_fp16.h>
#include <math.h>
#include <stdint.h>

// Shapes (fixed)
#define BB 8
#define SS 14
#define DD 2048
#define CC 20
#define WDIM 300
#define II 1024
#define NPOS 1568      // BB*SS*SS
#define PP 196         // SS*SS

#define MPAD 1664      // 26 * 64, >= NPOS

// Scratch (no allocation allowed -> __device__ globals)
__device__ float g_himg[NPOS * II];     // 6.4 MB
__device__ float g_hword[CC * II];
__device__ float g_w34[II];
__device__ float g_w34p[64 * II];
__device__ float g_b34;
__device__ float g_logits[NPOS * CC];
__device__ __align__(256) __half g_Ah[(size_t)MPAD * DD];
__device__ __align__(256) __half g_Bh[(size_t)II * DD];

// ---------------------------------------------------------------------------
// PTX helpers (base PTX only)
// ---------------------------------------------------------------------------
__device__ __forceinline__ uint32_t cvta_smem(const void* p) {
    uint32_t a;
    asm("{ .reg .u64 t; cvta.to.shared.u64 t, %1; cvt.u32.u64 %0, t; }"
        : "=r"(a) : "l"(p));
    return a;
}

__device__ __forceinline__ float fast_tanh(float x) {
    float r;
    asm("tanh.approx.f32 %0, %1;" : "=f"(r) : "f"(x));
    return r;
}

__device__ __forceinline__ void cp_async16(uint32_t s, const void* g) {
    asm volatile("cp.async.cg.shared.global [%0], [%1], 16;" :: "r"(s), "l"(g));
}
#define CP_COMMIT() asm volatile("cp.async.commit_group;" ::: "memory")
#define CP_WAIT1()  asm volatile("cp.async.wait_group 1;" ::: "memory")
#define CP_WAIT0()  asm volatile("cp.async.wait_group 0;" ::: "memory")

__device__ __forceinline__ void ldsm_x4(uint32_t* r, uint32_t addr) {
    asm volatile("ldmatrix.sync.aligned.m8n8.x4.shared.b16 {%0,%1,%2,%3}, [%4];"
                 : "=r"(r[0]), "=r"(r[1]), "=r"(r[2]), "=r"(r[3]) : "r"(addr));
}

__device__ __forceinline__ void mma_fp16(float* d, const uint32_t* a, const uint32_t* b) {
    asm volatile(
        "mma.sync.aligned.m16n8k16.row.col.f32.f16.f16.f32 "
        "{%0,%1,%2,%3}, {%4,%5,%6,%7}, {%8,%9}, {%0,%1,%2,%3};"
        : "+f"(d[0]), "+f"(d[1]), "+f"(d[2]), "+f"(d[3])
        : "r"(a[0]), "r"(a[1]), "r"(a[2]), "r"(a[3]), "r"(b[0]), "r"(b[1]));
}

// ---------------------------------------------------------------------------
// Conversion kernel: fp32 -> fp16 for both A (img, padded) and B (W1)
// ---------------------------------------------------------------------------
#define CONV_A_BLOCKS (MPAD * DD / 4 / 256)   // 3328
#define CONV_B_BLOCKS (II * DD / 4 / 256)     // 2048

__global__ __launch_bounds__(256) void k_conv(const float* __restrict__ img,
                                              const float* __restrict__ W1) {
    int blk = blockIdx.x;
    if (blk < CONV_A_BLOCKS) {
        size_t t = (size_t)blk * 256 + threadIdx.x;
        size_t base = t * 4;
        size_t row = base / DD;
        float4 v = make_float4(0.f, 0.f, 0.f, 0.f);
        if (row < NPOS) v = *(const float4*)&img[base];
        __half2 h0 = __floats2half2_rn(v.x, v.y);
        __half2 h1 = __floats2half2_rn(v.z, v.w);
        uint2 o;
        o.x = *reinterpret_cast<uint32_t*>(&h0);
        o.y = *reinterpret_cast<uint32_t*>(&h1);
        *(uint2*)&g_Ah[base] = o;
    } else {
        size_t t = (size_t)(blk - CONV_A_BLOCKS) * 256 + threadIdx.x;
        size_t base = t * 4;
        float4 v = *(const float4*)&W1[base];
        __half2 h0 = __floats2half2_rn(v.x, v.y);
        __half2 h1 = __floats2half2_rn(v.z, v.w);
        uint2 o;
        o.x = *reinterpret_cast<uint32_t*>(&h0);
        o.y = *reinterpret_cast<uint32_t*>(&h1);
        *(uint2*)&g_Bh[base] = o;
    }
}

// ---------------------------------------------------------------------------
// mma.sync fp16 GEMM: h_img[1568(pad1664), 1024] = A[M,2048] @ W1[1024,2048]^T
// BM=64, BN=64, BK=64, 3-stage cp.async (exactly 48KB), 128 threads (4 warps,
// 32x32 warp tiles). Grid (16, 26) = 416 CTAs. 32 K-iterations -> half the
// barriers of BK=32. XOR swizzle (chunk ^ row&7) on 128B rows: conflict-free
// ldmatrix + cp.async.
// ---------------------------------------------------------------------------
#define BK 64
#define TILE_B (64 * 128)             // 8192 bytes per matrix per stage
#define STAGE_BYTES (2 * TILE_B)      // 16384
#define NSTAGE 3
#define GEMM_SMEM (NSTAGE * STAGE_BYTES)    // 49152 = 48KB exactly
#define NK (DD / BK)                  // 32

__global__ __launch_bounds__(128) void k_gemm_mma() {
    extern __shared__ __align__(16) char dsm[];
    const uint32_t smem = cvta_smem(dsm);

    const int tid = threadIdx.x;
    const int wid = tid >> 5;
    const int lane = tid & 31;
    const int bm = blockIdx.y * 64;
    const int bn = blockIdx.x * 64;
    const int wm = (wid & 1) * 32;
    const int wn = (wid >> 1) * 32;

    // global->smem: 1024 16B chunks per stage, 8 per thread.
    // grow = tid/8 (0..15), gch = tid%8 (0..7); rows grow+16t, t=0..3 for A and B.
    const int grow = tid >> 3;
    const int gch = tid & 7;
    const __half* pA = &g_Ah[(size_t)(bm + grow) * DD + gch * 8];
    const __half* pB = &g_Bh[(size_t)(bn + grow) * DD + gch * 8];
    const uint32_t sA0 = (uint32_t)(grow * 128 + ((gch ^ (grow & 7)) * 16));
    const size_t gstep16 = (size_t)16 * DD;
    const uint32_t sstep16 = 16 * 128;   // 2048

    // ldmatrix offsets (XOR swizzle): chunk index = ks*2 + half
    uint32_t aoff[2][4], boff[2][4];
    {
        int r = lane & 15, c = lane >> 4;
        #pragma unroll
        for (int m = 0; m < 2; m++) {
            int row = wm + m * 16 + r;
            #pragma unroll
            for (int ks = 0; ks < 4; ks++)
                aoff[m][ks] = (uint32_t)(row * 128 + (((ks * 2 + c) ^ (row & 7)) * 16));
        }
        int br = ((lane >> 4) * 8) + (lane & 7);
        int bc = (lane >> 3) & 1;
        #pragma unroll
        for (int np = 0; np < 2; np++) {
            int row = wn + np * 16 + br;
            #pragma unroll
            for (int ks = 0; ks < 4; ks++)
                boff[np][ks] = (uint32_t)(row * 128 + (((ks * 2 + bc) ^ (row & 7)) * 16));
        }
    }

    float acc[2][4][4];
    #pragma unroll
    for (int i = 0; i < 2; i++)
        #pragma unroll
        for (int j = 0; j < 4; j++)
            #pragma unroll
            for (int q = 0; q < 4; q++) acc[i][j][q] = 0.f;

    auto load_stage = [&](int kc, int buf) {
        uint32_t sb = smem + buf * STAGE_BYTES;
        size_t go = (size_t)kc * BK;
        #pragma unroll
        for (int t = 0; t < 4; t++)
            cp_async16(sb + sA0 + t * sstep16, pA + go + t * gstep16);
        #pragma unroll
        for (int t = 0; t < 4; t++)
            cp_async16(sb + TILE_B + sA0 + t * sstep16, pB + go + t * gstep16);
    };

    load_stage(0, 0); CP_COMMIT();
    load_stage(1, 1); CP_COMMIT();

    int buf = 0;
    for (int it = 0; it < NK; it++) {
        if (it + 1 < NK) { CP_WAIT1(); } else { CP_WAIT0(); }
        __syncthreads();
        if (it + 2 < NK) { load_stage(it + 2, (buf + 2) % NSTAGE); CP_COMMIT(); }

        uint32_t sb = smem + buf * STAGE_BYTES;
        #pragma unroll
        for (int ks = 0; ks < 4; ks++) {
            uint32_t af[2][4];
            uint32_t bfr[4][2];
            #pragma unroll
            for (int m = 0; m < 2; m++)
                ldsm_x4(af[m], sb + aoff[m][ks]);
            #pragma unroll
            for (int np = 0; np < 2; np++) {
                uint32_t t4[4];
                ldsm_x4(t4, sb + TILE_B + boff[np][ks]);
                bfr[2 * np][0] = t4[0]; bfr[2 * np][1] = t4[1];
                bfr[2 * np + 1][0] = t4[2]; bfr[2 * np + 1][1] = t4[3];
            }
            #pragma unroll
            for (int m = 0; m < 2; m++)
                #pragma unroll
                for (int n = 0; n < 4; n++)
                    mma_fp16(acc[m][n], af[m], bfr[n]);
        }
        buf = (buf + 1) % NSTAGE;
    }

    // epilogue
    const int er = lane >> 2;
    const int ec = (lane & 3) * 2;
    #pragma unroll
    for (int m = 0; m < 2; m++) {
        int row0 = bm + wm + m * 16 + er;
        #pragma unroll
        for (int n = 0; n < 4; n++) {
            int col = bn + wn + n * 8 + ec;
            if (row0 < NPOS)
                *(float2*)&g_himg[(size_t)row0 * II + col] = make_float2(acc[m][n][0], acc[m][n][1]);
            if (row0 + 8 < NPOS)
                *(float2*)&g_himg[(size_t)(row0 + 8) * II + col] = make_float2(acc[m][n][2], acc[m][n][3]);
        }
    }
}

// ---------------------------------------------------------------------------
// K_hw: fused h_word + w34 partials (block-range dispatch)
//   blocks [0, 80):    h_word[c,i] = sum_d wordF[c,d] * W2[i,d]
//   blocks [80, 336):  w34 partials over 16-j chunks
// ---------------------------------------------------------------------------
#define HWORD_BLOCKS 80   // 4 x CC
#define HW_BLOCKS (HWORD_BLOCKS + 256)

__global__ __launch_bounds__(256) void k_hw(const float* __restrict__ wordF,
                                            const float* __restrict__ W2,
                                            const float* __restrict__ W3,
                                            const float* __restrict__ W4) {
    int blk = blockIdx.x;
    if (blk < HWORD_BLOCKS) {
        const int c = blk >> 2;
        const int i = (blk & 3) * 256 + threadIdx.x;
        __shared__ float sw[WDIM + 4];
        for (int d = threadIdx.x; d < WDIM; d += 256) sw[d] = wordF[c * WDIM + d];
        if (threadIdx.x < 4) sw[WDIM + threadIdx.x] = 0.f;
        __syncthreads();
        const float* w2r = &W2[(size_t)i * WDIM];
        float a0 = 0.f, a1 = 0.f, a2 = 0.f, a3 = 0.f;
        #pragma unroll 5
        for (int d = 0; d < WDIM; d += 4) {
            a0 += sw[d + 0] * w2r[d + 0];
            a1 += sw[d + 1] * w2r[d + 1];
            a2 += sw[d + 2] * w2r[d + 2];
            a3 += sw[d + 3] * w2r[d + 3];
        }
        g_hword[c * II + i] = (a0 + a1) + (a2 + a3);
    } else {
        blk -= HWORD_BLOCKS;
        const int i = (blk & 3) * 256 + threadIdx.x;
        const int jb = blk >> 2;
        const int j0 = jb * 16;
        float acc = 0.f;
        #pragma unroll
        for (int j = 0; j < 16; j++)
            acc += W4[j0 + j] * W3[(size_t)(j0 + j) * II + i];
        g_w34p[(size_t)jb * II + i] = acc;
    }
}

// K2b: reduce partials + b34
__global__ __launch_bounds__(256) void k_w34_red(const float* __restrict__ b3,
                                                 const float* __restrict__ W4,
                                                 const float* __restrict__ b4) {
    const int i = blockIdx.x * 256 + threadIdx.x;
    float s = 0.f;
    #pragma unroll 8
    for (int k = 0; k < 64; k++) s += g_w34p[(size_t)k * II + i];
    g_w34[i] = s;

    if (blockIdx.x == 0) {
        __shared__ float sred[256];
        float a = 0.f;
        for (int j = threadIdx.x; j < II; j += 256) a += W4[j] * b3[j];
        sred[threadIdx.x] = a;
        __syncthreads();
        for (int st = 128; st > 0; st >>= 1) {
            if (threadIdx.x < st) sred[threadIdx.x] += sred[threadIdx.x + st];
            __syncthreads();
        }
        if (threadIdx.x == 0) g_b34 = sred[0] + b4[0];
    }
}

// ---------------------------------------------------------------------------
// K4: logits[n,c] = sum_i tanh(h_img[n,i]*h_word[c,i]) * w34[i] + b34
// ---------------------------------------------------------------------------
__global__ __launch_bounds__(128) void k_logits() {
    const int n = blockIdx.x;
    const int tid = threadIdx.x;
    const int i0 = tid * 8;
    const int lane = tid & 31;
    const int warp = tid >> 5;

    float hi[8], wv[8];
    {
        const float4* hp = (const float4*)&g_himg[(size_t)n * II + i0];
        float4 h0 = hp[0], h1 = hp[1];
        hi[0] = h0.x; hi[1] = h0.y; hi[2] = h0.z; hi[3] = h0.w;
        hi[4] = h1.x; hi[5] = h1.y; hi[6] = h1.z; hi[7] = h1.w;
        const float4* wp = (const float4*)&g_w34[i0];
        float4 w0 = wp[0], w1 = wp[1];
        wv[0] = w0.x; wv[1] = w0.y; wv[2] = w0.z; wv[3] = w0.w;
        wv[4] = w1.x; wv[5] = w1.y; wv[6] = w1.z; wv[7] = w1.w;
    }

    __shared__ float red[CC * 4];

    for (int c = 0; c < CC; c++) {
        const float4* hwp = (const float4*)&g_hword[(size_t)c * II + i0];
        float4 w0 = hwp[0], w1 = hwp[1];
        float a = 0.f;
        a += fast_tanh(hi[0] * w0.x) * wv[0];
        a += fast_tanh(hi[1] * w0.y) * wv[1];
        a += fast_tanh(hi[2] * w0.z) * wv[2];
        a += fast_tanh(hi[3] * w0.w) * wv[3];
        a += fast_tanh(hi[4] * w1.x) * wv[4];
        a += fast_tanh(hi[5] * w1.y) * wv[5];
        a += fast_tanh(hi[6] * w1.z) * wv[6];
        a += fast_tanh(hi[7] * w1.w) * wv[7];
        a += __shfl_down_sync(0xffffffff, a, 16);
        a += __shfl_down_sync(0xffffffff, a, 8);
        a += __shfl_down_sync(0xffffffff, a, 4);
        a += __shfl_down_sync(0xffffffff, a, 2);
        a += __shfl_down_sync(0xffffffff, a, 1);
        if (lane == 0) red[c * 4 + warp] = a;
    }
    __syncthreads();
    if (tid < CC) {
        float l = red[tid * 4] + red[tid * 4 + 1] + red[tid * 4 + 2] + red[tid * 4 + 3] + g_b34;
        g_logits[n * CC + tid] = l;
    }
}

// ---------------------------------------------------------------------------
// K5: softmax over 196 spatial positions per (b,c); one block per (b,c)
// ---------------------------------------------------------------------------
__global__ __launch_bounds__(256) void k_softmax(float* __restrict__ out_coef) {
    const int b = blockIdx.x / CC;
    const int c = blockIdx.x % CC;
    const int tid = threadIdx.x;
    const int lane = tid & 31;
    const int warp = tid >> 5;
    __shared__ float sm[8];

    float v = -1e30f;
    if (tid < PP) v = g_logits[((size_t)b * PP + tid) * CC + c];

    float m = v;
    m = fmaxf(m, __shfl_xor_sync(0xffffffff, m, 16));
    m = fmaxf(m, __shfl_xor_sync(0xffffffff, m, 8));
    m = fmaxf(m, __shfl_xor_sync(0xffffffff, m, 4));
    m = fmaxf(m, __shfl_xor_sync(0xffffffff, m, 2));
    m = fmaxf(m, __shfl_xor_sync(0xffffffff, m, 1));
    if (lane == 0) sm[warp] = m;
    __syncthreads();
    if (warp == 0) {
        float t = sm[lane & 7];
        t = fmaxf(t, __shfl_xor_sync(0xffffffff, t, 4));
        t = fmaxf(t, __shfl_xor_sync(0xffffffff, t, 2));
        t = fmaxf(t, __shfl_xor_sync(0xffffffff, t, 1));
        if (lane == 0) sm[0] = t;
    }
    __syncthreads();
    const float mx = sm[0];
    __syncthreads();

    float e = (tid < PP) ? expf(v - mx) : 0.f;
    float s = e;
    s += __shfl_xor_sync(0xffffffff, s, 16);
    s += __shfl_xor_sync(0xffffffff, s, 8);
    s += __shfl_xor_sync(0xffffffff, s, 4);
    s += __shfl_xor_sync(0xffffffff, s, 2);
    s += __shfl_xor_sync(0xffffffff, s, 1);
    if (lane == 0) sm[warp] = s;
    __syncthreads();
    if (warp == 0) {
        float t = sm[lane & 7];
        t += __shfl_xor_sync(0xffffffff, t, 4);
        t += __shfl_xor_sync(0xffffffff, t, 2);
        t += __shfl_xor_sync(0xffffffff, t, 1);
        if (lane == 0) sm[0] = t;
    }
    __syncthreads();
    const float inv = 1.f / sm[0];

    if (tid < PP) out_coef[((size_t)b * PP + tid) * CC + c] = e * inv;
}

// ---------------------------------------------------------------------------
// K6: fmwc[b,s1,s2,c,d] = img[b,s1,s2,d] * coef[b,s1,s2,c]
// grid (NPOS, 2): blockIdx.y picks classes [y*10, y*10+10). Streaming stores.
// ---------------------------------------------------------------------------
__global__ __launch_bounds__(256) void k_fmwc(const float* __restrict__ img,
                                              const float* __restrict__ coef,
                                              float* __restrict__ out_fmwc) {
    const int n = blockIdx.x;
    const int ch = blockIdx.y;            // 0 or 1
    const int tid = threadIdx.x;
    __shared__ float4 simg[DD / 4];
    __shared__ float sc[CC / 2];
    const float4* ip = (const float4*)&img[(size_t)n * DD];
    simg[tid] = ip[tid];
    simg[tid + 256] = ip[tid + 256];
    if (tid < CC / 2) sc[tid] = coef[(size_t)n * CC + ch * (CC / 2) + tid];
    __syncthreads();

    float4* op = (float4*)&out_fmwc[(size_t)n * CC * DD + (size_t)ch * (CC / 2) * DD];
    #pragma unroll 5
    for (int idx = tid; idx < (CC / 2) * (DD / 4); idx += 256) {
        int c = idx >> 9;
        int d = idx & 511;
        float4 v = simg[d];
        float s = sc[c];
        __stcs(&op[idx], make_float4(v.x * s, v.y * s, v.z * s, v.w * s));
    }
}

// ---------------------------------------------------------------------------
// K7: semantic[b,c,d] = sum_p coef[b,p,c] * img[b,p,d]
// ---------------------------------------------------------------------------
__global__ __launch_bounds__(256) void k_semantic(const float* __restrict__ img,
                                                  const float* __restrict__ coef,
                                                  float* __restrict__ out_sem) {
    const int b = blockIdx.y;
    const int d = blockIdx.x * 256 + threadIdx.x;
    __shared__ float4 scoef[PP * CC / 4];
    const float4* cp = (const float4*)&coef[(size_t)b * PP * CC];
    for (int idx = threadIdx.x; idx < PP * CC / 4; idx += 256) scoef[idx] = cp[idx];
    __syncthreads();

    float acc[CC];
    #pragma unroll
    for (int c = 0; c < CC; c++) acc[c] = 0.f;

    const float* ip = &img[(size_t)b * PP * DD + d];
    #pragma unroll 2
    for (int p = 0; p < PP; p++) {
        float v = ip[(size_t)p * DD];
        #pragma unroll
        for (int c4 = 0; c4 < 5; c4++) {
            float4 cf = scoef[p * 5 + c4];
            acc[c4 * 4 + 0] += cf.x * v;
            acc[c4 * 4 + 1] += cf.y * v;
            acc[c4 * 4 + 2] += cf.z * v;
            acc[c4 * 4 + 3] += cf.w * v;
        }
    }
    #pragma unroll
    for (int c = 0; c < CC; c++)
        out_sem[((size_t)b * CC + c) * DD + d] = acc[c];
}

// ---------------------------------------------------------------------------
extern "C" void kernel_launch(void* const* d_in, const int* in_sizes, int n_in,
                              void* d_out, int out_size) {
    const float* img   = (const float*)d_in[0];  // [8,14,14,2048]
    const float* wordF = (const float*)d_in[1];  // [20,300]
    const float* W1    = (const float*)d_in[2];  // [1024,2048]
    const float* W2    = (const float*)d_in[3];  // [1024,300]
    const float* W3    = (const float*)d_in[4];  // [1024,1024]
    const float* b3    = (const float*)d_in[5];  // [1024]
    const float* W4    = (const float*)d_in[6];  // [1,1024]
    const float* b4    = (const float*)d_in[7];  // [1]

    float* out = (float*)d_out;
    float* out_sem  = out;                                      // 8*20*2048
    float* out_fmwc = out_sem + (size_t)BB * CC * DD;           // 8*14*14*20*2048
    float* out_coef = out_fmwc + (size_t)NPOS * CC * DD;        // 8*14*14*20

    // GEMM kept as the 4th launch for the fixed ncu capture slot.
    k_conv<<<CONV_A_BLOCKS + CONV_B_BLOCKS, 256>>>(img, W1);    // 1
    k_hw<<<HW_BLOCKS, 256>>>(wordF, W2, W3, W4);                // 2
    k_w34_red<<<4, 256>>>(b3, W4, b4);                          // 3
    k_gemm_mma<<<dim3(II / 64, MPAD / 64), 128, GEMM_SMEM>>>(); // 4 <- profiled
    k_logits<<<NPOS, 128>>>();                                  // 5
    k_softmax<<<BB * CC, 256>>>(out_coef);                      // 6
    k_fmwc<<<dim3(NPOS, 2), 256>>>(img, out_coef, out_fmwc);    // 7
    k_semantic<<<dim3(DD / 256, BB), 256>>>(img, out_coef, out_sem); // 8
}

// round 17
// speedup vs baseline: 1.2930x; 1.2930x over previous
#include <cuda_runtime.h>
#include <cuda_fp16.h>
#include <math.h>
#include <stdint.h>

// Shapes (fixed)
#define BB 8
#define SS 14
#define DD 2048
#define CC 20
#define WDIM 300
#define II 1024
#define NPOS 1568      // BB*SS*SS
#define PP 196         // SS*SS

#define MPAD 1664      // 26 * 64, >= NPOS

// Scratch (no allocation allowed -> __device__ globals)
__device__ float g_himg[NPOS * II];     // 6.4 MB
__device__ float g_hword[CC * II];
__device__ float g_w34[II];
__device__ float g_w34p[64 * II];
__device__ float g_b34;
__device__ float g_logits[NPOS * CC];
__device__ __align__(256) __half g_Ah[(size_t)MPAD * DD];
__device__ __align__(256) __half g_Bh[(size_t)II * DD];

// ---------------------------------------------------------------------------
// PTX helpers (base PTX only)
// ---------------------------------------------------------------------------
__device__ __forceinline__ uint32_t cvta_smem(const void* p) {
    uint32_t a;
    asm("{ .reg .u64 t; cvta.to.shared.u64 t, %1; cvt.u32.u64 %0, t; }"
        : "=r"(a) : "l"(p));
    return a;
}

__device__ __forceinline__ float fast_tanh(float x) {
    float r;
    asm("tanh.approx.f32 %0, %1;" : "=f"(r) : "f"(x));
    return r;
}

__device__ __forceinline__ void cp_async16(uint32_t s, const void* g) {
    asm volatile("cp.async.cg.shared.global [%0], [%1], 16;" :: "r"(s), "l"(g));
}
#define CP_COMMIT() asm volatile("cp.async.commit_group;" ::: "memory")
#define CP_WAIT2()  asm volatile("cp.async.wait_group 2;" ::: "memory")
#define CP_WAIT1()  asm volatile("cp.async.wait_group 1;" ::: "memory")
#define CP_WAIT0()  asm volatile("cp.async.wait_group 0;" ::: "memory")

__device__ __forceinline__ void ldsm_x4(uint32_t* r, uint32_t addr) {
    asm volatile("ldmatrix.sync.aligned.m8n8.x4.shared.b16 {%0,%1,%2,%3}, [%4];"
                 : "=r"(r[0]), "=r"(r[1]), "=r"(r[2]), "=r"(r[3]) : "r"(addr));
}

__device__ __forceinline__ void mma_fp16(float* d, const uint32_t* a, const uint32_t* b) {
    asm volatile(
        "mma.sync.aligned.m16n8k16.row.col.f32.f16.f16.f32 "
        "{%0,%1,%2,%3}, {%4,%5,%6,%7}, {%8,%9}, {%0,%1,%2,%3};"
        : "+f"(d[0]), "+f"(d[1]), "+f"(d[2]), "+f"(d[3])
        : "r"(a[0]), "r"(a[1]), "r"(a[2]), "r"(a[3]), "r"(b[0]), "r"(b[1]));
}

// ---------------------------------------------------------------------------
// Conversion kernel: fp32 -> fp16 for both A (img, padded) and B (W1)
// ---------------------------------------------------------------------------
#define CONV_A_BLOCKS (MPAD * DD / 4 / 256)   // 3328
#define CONV_B_BLOCKS (II * DD / 4 / 256)     // 2048

__global__ __launch_bounds__(256) void k_conv(const float* __restrict__ img,
                                              const float* __restrict__ W1) {
    int blk = blockIdx.x;
    if (blk < CONV_A_BLOCKS) {
        size_t t = (size_t)blk * 256 + threadIdx.x;
        size_t base = t * 4;
        size_t row = base / DD;
        float4 v = make_float4(0.f, 0.f, 0.f, 0.f);
        if (row < NPOS) v = *(const float4*)&img[base];
        __half2 h0 = __floats2half2_rn(v.x, v.y);
        __half2 h1 = __floats2half2_rn(v.z, v.w);
        uint2 o;
        o.x = *reinterpret_cast<uint32_t*>(&h0);
        o.y = *reinterpret_cast<uint32_t*>(&h1);
        *(uint2*)&g_Ah[base] = o;
    } else {
        size_t t = (size_t)(blk - CONV_A_BLOCKS) * 256 + threadIdx.x;
        size_t base = t * 4;
        float4 v = *(const float4*)&W1[base];
        __half2 h0 = __floats2half2_rn(v.x, v.y);
        __half2 h1 = __floats2half2_rn(v.z, v.w);
        uint2 o;
        o.x = *reinterpret_cast<uint32_t*>(&h0);
        o.y = *reinterpret_cast<uint32_t*>(&h1);
        *(uint2*)&g_Bh[base] = o;
    }
}

// ---------------------------------------------------------------------------
// mma.sync fp16 GEMM: h_img[1568(pad1664), 1024] = A[M,2048] @ W1[1024,2048]^T
// BM=64, BN=64, BK=32, 4-stage cp.async, 128 threads (4 warps, 32x32 tiles).
// Grid (16, 26) = 416 CTAs. Rows padded to 80B -> conflict-free ldmatrix.
// ---------------------------------------------------------------------------
#define BK 32
#define ROWB 80
#define A_TILE_B (64 * ROWB)          // 5120
#define B_TILE_B (64 * ROWB)          // 5120
#define STAGE_BYTES (A_TILE_B + B_TILE_B)   // 10240
#define NSTAGE 4
#define GEMM_SMEM (NSTAGE * STAGE_BYTES)    // 40960
#define NK (DD / BK)                  // 64

#define A_OFF 0
#define B_OFF A_TILE_B

__global__ __launch_bounds__(128) void k_gemm_mma() {
    extern __shared__ __align__(16) char dsm[];
    const uint32_t smem = cvta_smem(dsm);

    const int tid = threadIdx.x;
    const int wid = tid >> 5;
    const int lane = tid & 31;
    const int bm = blockIdx.y * 64;
    const int bn = blockIdx.x * 64;
    const int wm = (wid & 1) * 32;
    const int wn = (wid >> 1) * 32;

    const int r0 = tid >> 2;
    const int gch = tid & 3;
    const __half* pA = &g_Ah[(size_t)(bm + r0) * DD + gch * 8];
    const __half* pB = &g_Bh[(size_t)(bn + r0) * DD + gch * 8];
    const uint32_t sA = (uint32_t)(r0 * ROWB + gch * 16);
    const size_t gstep32 = (size_t)32 * DD;
    const uint32_t sstep32 = 32 * ROWB;

    uint32_t aoff[2][2], boff[2][2];
    {
        int r = lane & 15, c = lane >> 4;
        #pragma unroll
        for (int m = 0; m < 2; m++)
            #pragma unroll
            for (int ks = 0; ks < 2; ks++)
                aoff[m][ks] = (uint32_t)((wm + m * 16 + r) * ROWB + ks * 32 + c * 16);
        int br = ((lane >> 4) * 8) + (lane & 7);
        int bc = (lane >> 3) & 1;
        #pragma unroll
        for (int np = 0; np < 2; np++)
            #pragma unroll
            for (int ks = 0; ks < 2; ks++)
                boff[np][ks] = (uint32_t)((wn + np * 16 + br) * ROWB + ks * 32 + bc * 16);
    }

    float acc[2][4][4];
    #pragma unroll
    for (int i = 0; i < 2; i++)
        #pragma unroll
        for (int j = 0; j < 4; j++)
            #pragma unroll
            for (int q = 0; q < 4; q++) acc[i][j][q] = 0.f;

    auto load_stage = [&](int kc, int buf) {
        uint32_t sb = smem + buf * STAGE_BYTES;
        size_t go = (size_t)kc * BK;
        #pragma unroll
        for (int t = 0; t < 2; t++)
            cp_async16(sb + A_OFF + sA + t * sstep32, pA + go + t * gstep32);
        #pragma unroll
        for (int t = 0; t < 2; t++)
            cp_async16(sb + B_OFF + sA + t * sstep32, pB + go + t * gstep32);
    };

    load_stage(0, 0); CP_COMMIT();
    load_stage(1, 1); CP_COMMIT();
    load_stage(2, 2); CP_COMMIT();

    int buf = 0;
    for (int it = 0; it < NK; it++) {
        const int pend = (NK - it < 3) ? (NK - it) : 3;
        if (pend == 3) { CP_WAIT2(); }
        else if (pend == 2) { CP_WAIT1(); }
        else { CP_WAIT0(); }
        __syncthreads();
        if (it + 3 < NK) { load_stage(it + 3, (buf + 3) & 3); CP_COMMIT(); }

        uint32_t sb = smem + buf * STAGE_BYTES;
        #pragma unroll
        for (int ks = 0; ks < 2; ks++) {
            uint32_t af[2][4];
            uint32_t bfr[4][2];
            #pragma unroll
            for (int m = 0; m < 2; m++)
                ldsm_x4(af[m], sb + A_OFF + aoff[m][ks]);
            #pragma unroll
            for (int np = 0; np < 2; np++) {
                uint32_t t4[4];
                ldsm_x4(t4, sb + B_OFF + boff[np][ks]);
                bfr[2 * np][0] = t4[0]; bfr[2 * np][1] = t4[1];
                bfr[2 * np + 1][0] = t4[2]; bfr[2 * np + 1][1] = t4[3];
            }
            #pragma unroll
            for (int m = 0; m < 2; m++)
                #pragma unroll
                for (int n = 0; n < 4; n++)
                    mma_fp16(acc[m][n], af[m], bfr[n]);
        }
        buf = (buf + 1) & 3;
    }

    // epilogue
    const int er = lane >> 2;
    const int ec = (lane & 3) * 2;
    #pragma unroll
    for (int m = 0; m < 2; m++) {
        int row0 = bm + wm + m * 16 + er;
        #pragma unroll
        for (int n = 0; n < 4; n++) {
            int col = bn + wn + n * 8 + ec;
            if (row0 < NPOS)
                *(float2*)&g_himg[(size_t)row0 * II + col] = make_float2(acc[m][n][0], acc[m][n][1]);
            if (row0 + 8 < NPOS)
                *(float2*)&g_himg[(size_t)(row0 + 8) * II + col] = make_float2(acc[m][n][2], acc[m][n][3]);
        }
    }
}

// ---------------------------------------------------------------------------
// K1: h_word[c,i] = sum_d wordF[c,d] * W2[i,d]   grid (4, CC)
// ---------------------------------------------------------------------------
__global__ __launch_bounds__(256) void k_hword(const float* __restrict__ wordF,
                                               const float* __restrict__ W2) {
    const int c = blockIdx.y;
    const int i = blockIdx.x * 256 + threadIdx.x;
    __shared__ float sw[WDIM + 4];
    for (int d = threadIdx.x; d < WDIM; d += 256) sw[d] = wordF[c * WDIM + d];
    if (threadIdx.x < 4) sw[WDIM + threadIdx.x] = 0.f;
    __syncthreads();
    const float* w2r = &W2[(size_t)i * WDIM];
    float a0 = 0.f, a1 = 0.f, a2 = 0.f, a3 = 0.f;
    #pragma unroll 5
    for (int d = 0; d < WDIM; d += 4) {
        a0 += sw[d + 0] * w2r[d + 0];
        a1 += sw[d + 1] * w2r[d + 1];
        a2 += sw[d + 2] * w2r[d + 2];
        a3 += sw[d + 3] * w2r[d + 3];
    }
    g_hword[c * II + i] = (a0 + a1) + (a2 + a3);
}

// ---------------------------------------------------------------------------
// K2a: partial w34. grid (4 i-chunks, 64 j-chunks); one i per thread.
// ---------------------------------------------------------------------------
__global__ __launch_bounds__(256) void k_w34_part(const float* __restrict__ W3,
                                                  const float* __restrict__ W4) {
    const int i = blockIdx.x * 256 + threadIdx.x;   // 0..1023
    const int jb = blockIdx.y;                      // 0..63
    const int j0 = jb * 16;
    float acc = 0.f;
    #pragma unroll
    for (int j = 0; j < 16; j++)
        acc += W4[j0 + j] * W3[(size_t)(j0 + j) * II + i];
    g_w34p[(size_t)jb * II + i] = acc;
}

// K2b: reduce partials + b34
__global__ __launch_bounds__(256) void k_w34_red(const float* __restrict__ b3,
                                                 const float* __restrict__ W4,
                                                 const float* __restrict__ b4) {
    const int i = blockIdx.x * 256 + threadIdx.x;
    float s = 0.f;
    #pragma unroll 8
    for (int k = 0; k < 64; k++) s += g_w34p[(size_t)k * II + i];
    g_w34[i] = s;

    if (blockIdx.x == 0) {
        __shared__ float sred[256];
        float a = 0.f;
        for (int j = threadIdx.x; j < II; j += 256) a += W4[j] * b3[j];
        sred[threadIdx.x] = a;
        __syncthreads();
        for (int st = 128; st > 0; st >>= 1) {
            if (threadIdx.x < st) sred[threadIdx.x] += sred[threadIdx.x + st];
            __syncthreads();
        }
        if (threadIdx.x == 0) g_b34 = sred[0] + b4[0];
    }
}

// ---------------------------------------------------------------------------
// K4: logits[n,c] = sum_i tanh(h_img[n,i]*h_word[c,i]) * w34[i] + b34
// ---------------------------------------------------------------------------
__global__ __launch_bounds__(128) void k_logits() {
    const int n = blockIdx.x;
    const int tid = threadIdx.x;
    const int i0 = tid * 8;
    const int lane = tid & 31;
    const int warp = tid >> 5;

    float hi[8], wv[8];
    {
        const float4* hp = (const float4*)&g_himg[(size_t)n * II + i0];
        float4 h0 = hp[0], h1 = hp[1];
        hi[0] = h0.x; hi[1] = h0.y; hi[2] = h0.z; hi[3] = h0.w;
        hi[4] = h1.x; hi[5] = h1.y; hi[6] = h1.z; hi[7] = h1.w;
        const float4* wp = (const float4*)&g_w34[i0];
        float4 w0 = wp[0], w1 = wp[1];
        wv[0] = w0.x; wv[1] = w0.y; wv[2] = w0.z; wv[3] = w0.w;
        wv[4] = w1.x; wv[5] = w1.y; wv[6] = w1.z; wv[7] = w1.w;
    }

    __shared__ float red[CC * 4];

    for (int c = 0; c < CC; c++) {
        const float4* hwp = (const float4*)&g_hword[(size_t)c * II + i0];
        float4 w0 = hwp[0], w1 = hwp[1];
        float a = 0.f;
        a += fast_tanh(hi[0] * w0.x) * wv[0];
        a += fast_tanh(hi[1] * w0.y) * wv[1];
        a += fast_tanh(hi[2] * w0.z) * wv[2];
        a += fast_tanh(hi[3] * w0.w) * wv[3];
        a += fast_tanh(hi[4] * w1.x) * wv[4];
        a += fast_tanh(hi[5] * w1.y) * wv[5];
        a += fast_tanh(hi[6] * w1.z) * wv[6];
        a += fast_tanh(hi[7] * w1.w) * wv[7];
        a += __shfl_down_sync(0xffffffff, a, 16);
        a += __shfl_down_sync(0xffffffff, a, 8);
        a += __shfl_down_sync(0xffffffff, a, 4);
        a += __shfl_down_sync(0xffffffff, a, 2);
        a += __shfl_down_sync(0xffffffff, a, 1);
        if (lane == 0) red[c * 4 + warp] = a;
    }
    __syncthreads();
    if (tid < CC) {
        float l = red[tid * 4] + red[tid * 4 + 1] + red[tid * 4 + 2] + red[tid * 4 + 3] + g_b34;
        g_logits[n * CC + tid] = l;
    }
}

// ---------------------------------------------------------------------------
// K5: softmax over 196 spatial positions per (b,c); one block per (b,c)
// ---------------------------------------------------------------------------
__global__ __launch_bounds__(256) void k_softmax(float* __restrict__ out_coef) {
    const int b = blockIdx.x / CC;
    const int c = blockIdx.x % CC;
    const int tid = threadIdx.x;
    const int lane = tid & 31;
    const int warp = tid >> 5;
    __shared__ float sm[8];

    float v = -1e30f;
    if (tid < PP) v = g_logits[((size_t)b * PP + tid) * CC + c];

    float m = v;
    m = fmaxf(m, __shfl_xor_sync(0xffffffff, m, 16));
    m = fmaxf(m, __shfl_xor_sync(0xffffffff, m, 8));
    m = fmaxf(m, __shfl_xor_sync(0xffffffff, m, 4));
    m = fmaxf(m, __shfl_xor_sync(0xffffffff, m, 2));
    m = fmaxf(m, __shfl_xor_sync(0xffffffff, m, 1));
    if (lane == 0) sm[warp] = m;
    __syncthreads();
    if (warp == 0) {
        float t = sm[lane & 7];
        t = fmaxf(t, __shfl_xor_sync(0xffffffff, t, 4));
        t = fmaxf(t, __shfl_xor_sync(0xffffffff, t, 2));
        t = fmaxf(t, __shfl_xor_sync(0xffffffff, t, 1));
        if (lane == 0) sm[0] = t;
    }
    __syncthreads();
    const float mx = sm[0];
    __syncthreads();

    float e = (tid < PP) ? expf(v - mx) : 0.f;
    float s = e;
    s += __shfl_xor_sync(0xffffffff, s, 16);
    s += __shfl_xor_sync(0xffffffff, s, 8);
    s += __shfl_xor_sync(0xffffffff, s, 4);
    s += __shfl_xor_sync(0xffffffff, s, 2);
    s += __shfl_xor_sync(0xffffffff, s, 1);
    if (lane == 0) sm[warp] = s;
    __syncthreads();
    if (warp == 0) {
        float t = sm[lane & 7];
        t += __shfl_xor_sync(0xffffffff, t, 4);
        t += __shfl_xor_sync(0xffffffff, t, 2);
        t += __shfl_xor_sync(0xffffffff, t, 1);
        if (lane == 0) sm[0] = t;
    }
    __syncthreads();
    const float inv = 1.f / sm[0];

    if (tid < PP) out_coef[((size_t)b * PP + tid) * CC + c] = e * inv;
}

// ---------------------------------------------------------------------------
// K6: fmwc[b,s1,s2,c,d] = img[b,s1,s2,d] * coef[b,s1,s2,c]
// grid (NPOS, 2): blockIdx.y picks classes [y*10, y*10+10). Streaming stores.
// ---------------------------------------------------------------------------
__global__ __launch_bounds__(256) void k_fmwc(const float* __restrict__ img,
                                              const float* __restrict__ coef,
                                              float* __restrict__ out_fmwc) {
    const int n = blockIdx.x;
    const int ch = blockIdx.y;            // 0 or 1
    const int tid = threadIdx.x;
    __shared__ float4 simg[DD / 4];
    __shared__ float sc[CC / 2];
    const float4* ip = (const float4*)&img[(size_t)n * DD];
    simg[tid] = ip[tid];
    simg[tid + 256] = ip[tid + 256];
    if (tid < CC / 2) sc[tid] = coef[(size_t)n * CC + ch * (CC / 2) + tid];
    __syncthreads();

    float4* op = (float4*)&out_fmwc[(size_t)n * CC * DD + (size_t)ch * (CC / 2) * DD];
    #pragma unroll 5
    for (int idx = tid; idx < (CC / 2) * (DD / 4); idx += 256) {
        int c = idx >> 9;
        int d = idx & 511;
        float4 v = simg[d];
        float s = sc[c];
        __stcs(&op[idx], make_float4(v.x * s, v.y * s, v.z * s, v.w * s));
    }
}

// ---------------------------------------------------------------------------
// K7: semantic[b,c,d] = sum_p coef[b,p,c] * img[b,p,d]
// ---------------------------------------------------------------------------
__global__ __launch_bounds__(256) void k_semantic(const float* __restrict__ img,
                                                  const float* __restrict__ coef,
                                                  float* __restrict__ out_sem) {
    const int b = blockIdx.y;
    const int d = blockIdx.x * 256 + threadIdx.x;
    __shared__ float4 scoef[PP * CC / 4];
    const float4* cp = (const float4*)&coef[(size_t)b * PP * CC];
    for (int idx = threadIdx.x; idx < PP * CC / 4; idx += 256) scoef[idx] = cp[idx];
    __syncthreads();

    float acc[CC];
    #pragma unroll
    for (int c = 0; c < CC; c++) acc[c] = 0.f;

    const float* ip = &img[(size_t)b * PP * DD + d];
    #pragma unroll 2
    for (int p = 0; p < PP; p++) {
        float v = ip[(size_t)p * DD];
        #pragma unroll
        for (int c4 = 0; c4 < 5; c4++) {
            float4 cf = scoef[p * 5 + c4];
            acc[c4 * 4 + 0] += cf.x * v;
            acc[c4 * 4 + 1] += cf.y * v;
            acc[c4 * 4 + 2] += cf.z * v;
            acc[c4 * 4 + 3] += cf.w * v;
        }
    }
    #pragma unroll
    for (int c = 0; c < CC; c++)
        out_sem[((size_t)b * CC + c) * DD + d] = acc[c];
}

// ---------------------------------------------------------------------------
extern "C" void kernel_launch(void* const* d_in, const int* in_sizes, int n_in,
                              void* d_out, int out_size) {
    const float* img   = (const float*)d_in[0];  // [8,14,14,2048]
    const float* wordF = (const float*)d_in[1];  // [20,300]
    const float* W1    = (const float*)d_in[2];  // [1024,2048]
    const float* W2    = (const float*)d_in[3];  // [1024,300]
    const float* W3    = (const float*)d_in[4];  // [1024,1024]
    const float* b3    = (const float*)d_in[5];  // [1024]
    const float* W4    = (const float*)d_in[6];  // [1,1024]
    const float* b4    = (const float*)d_in[7];  // [1]

    float* out = (float*)d_out;
    float* out_sem  = out;                                      // 8*20*2048
    float* out_fmwc = out_sem + (size_t)BB * CC * DD;           // 8*14*14*20*2048
    float* out_coef = out_fmwc + (size_t)NPOS * CC * DD;        // 8*14*14*20

    // GEMM kept as the 4th launch for the fixed ncu capture slot.
    k_conv<<<CONV_A_BLOCKS + CONV_B_BLOCKS, 256>>>(img, W1);    // 1
    k_hword<<<dim3(4, CC), 256>>>(wordF, W2);                   // 2
    k_w34_part<<<dim3(4, 64), 256>>>(W3, W4);                   // 3
    k_gemm_mma<<<dim3(II / 64, MPAD / 64), 128, GEMM_SMEM>>>(); // 4 <- profiled
    k_w34_red<<<4, 256>>>(b3, W4, b4);                          // 5
    k_logits<<<NPOS, 128>>>();                                  // 6
    k_softmax<<<BB * CC, 256>>>(out_coef);                      // 7
    k_fmwc<<<dim3(NPOS, 2), 256>>>(img, out_coef, out_fmwc);    // 8
    k_semantic<<<dim3(DD / 256, BB), 256>>>(img, out_coef, out_sem); // 9
}